// round 7
// baseline (speedup 1.0000x reference)
#include <cuda_runtime.h>
#include <cstdint>

// Problem constants (match reference)
#define BATCH 256
#define NSRC  10
#define NMC_C 16
#define LL_C  128
#define PLANE (LL_C * LL_C)          // 16384 floats per channel plane
#define PLANE4 (PLANE / 4)           // 4096 float4 per plane
#define TPB   256
#define STORES_PER_THREAD (PLANE4 / TPB)   // 16

// One block per (batch, channel) plane. grid = BATCH * 2*NMC_C = 8192.
// Threads 0..NSRC-1 compute the scatter indices for this batch, keep only
// the points whose mass bin matches this block's channel (usually 0 or 1),
// and publish their plane offsets to smem. After ONE barrier, all threads
// stream the plane with float4 stores, patching the override lanes
// in-register. Every output byte is written exactly once.
__global__ void __launch_bounds__(TPB) fused_kernel(
    const float* __restrict__ coord,
    const float* __restrict__ lows,
    const float* __restrict__ highs,
    float* __restrict__ out)
{
    __shared__ int s_offs[NSRC];   // plane offsets of overrides for this channel
    __shared__ int s_cnt;

    int blk = blockIdx.x;
    int b   = blk >> 5;           // batch
    int ch  = blk & 31;           // channel 0..31
    int t   = threadIdx.x;

    if (t == 0) s_cnt = 0;
    __syncthreads();

    // --- index computation (threads 0..9) ---
    if (t < NSRC) {
        const float* c = coord + (size_t)b * (3 * NSRC) + t * 3;
        float lo0 = lows[0], lo1 = lows[1], lo2 = lows[2];
        float hi0 = highs[0], hi1 = highs[1], hi2 = highs[2];

        float xg = (c[0]         - lo0) / (hi0 - lo0);
        float yg = (c[1]         - lo1) / (hi1 - lo1);
        float mg = (log10f(c[2]) - lo2) / (hi2 - lo2);

        int xi = (int)floorf(xg * (float)LL_C);
        int yi = (int)floorf(yg * (float)LL_C);
        int mi = (int)floorf(mg * (float)NMC_C);

        bool ok = ((unsigned)xi < LL_C) & ((unsigned)yi < LL_C) &
                  ((unsigned)mi < NMC_C) & (mi == (ch & (NMC_C - 1)));
        if (ok) {
            int slot = atomicAdd(&s_cnt, 1);
            s_offs[slot] = yi * LL_C + xi;
        }
    }
    __syncthreads();

    int cnt = s_cnt;
    float v  = (ch < NMC_C) ? 1.0f : 0.0f;   // background value
    float ov = 1.0f - v;                      // override value
    float4* p = (float4*)(out + (size_t)blk * PLANE);

    if (cnt == 0) {
        // fast path: pure streaming store, no per-store checks
        float4 vv = make_float4(v, v, v, v);
#pragma unroll
        for (int k = 0; k < STORES_PER_THREAD; k++)
            p[t + k * TPB] = vv;
    } else {
#pragma unroll
        for (int k = 0; k < STORES_PER_THREAD; k++) {
            float4 val = make_float4(v, v, v, v);
            int base4 = t + k * TPB;        // float4 index in plane
            for (int j = 0; j < cnt; j++) {
                int o = s_offs[j];
                if ((o >> 2) == base4)
                    ((float*)&val)[o & 3] = ov;
            }
            p[base4] = val;
        }
    }
}

extern "C" void kernel_launch(void* const* d_in, const int* in_sizes, int n_in,
                              void* d_out, int out_size) {
    const float* coord = (const float*)d_in[0];
    const float* lows  = (const float*)d_in[1];
    const float* highs = (const float*)d_in[2];
    float* out = (float*)d_out;

    fused_kernel<<<BATCH * 2 * NMC_C, TPB>>>(coord, lows, highs, out);
}